// round 6
// baseline (speedup 1.0000x reference)
#include <cuda_runtime.h>
#include <cuda_fp16.h>
#include <cuda_bf16.h>
#include <cstdint>
#include <cstddef>

#define N_SRC   100000
#define N_OUT   100000
#define N_EDGES 1600000
#define C       128

// ---------------- scratch (device globals; no allocation allowed) ------------
__device__ __half g_Wxh[(size_t)N_SRC * C];  // node-major fp16 Wx, 25.6 MB
__device__ float  g_num[(size_t)N_OUT * C];  // node-major accumulators, 51.2 MB
__device__ float  g_expa[N_SRC];
__device__ float  g_den[N_OUT];
__device__ int    g_cnt[N_SRC];              // per-src edge counts
__device__ int    g_off[N_SRC + 1];          // CSR offsets by src
__device__ int    g_cur[N_SRC];
__device__ int    g_tgts[N_EDGES];           // tgt list grouped by src

// ---------------- kernel 1: zero accumulators + counters ---------------------
__global__ void zero_kernel()
{
    size_t i      = (size_t)blockIdx.x * blockDim.x + threadIdx.x;
    size_t stride = (size_t)gridDim.x * blockDim.x;
    float4* np = reinterpret_cast<float4*>(g_num);
    const size_t n4 = (size_t)N_OUT * C / 4;
    for (size_t k = i; k < n4; k += stride)
        np[k] = make_float4(0.f, 0.f, 0.f, 0.f);
    for (size_t k = i; k < N_OUT; k += stride)
        g_den[k] = 0.f;
    for (size_t k = i; k < N_SRC; k += stride)
        g_cnt[k] = 0;
}

// ---------------- kernel 2: histogram of sources (2-edge ILP) ----------------
__global__ __launch_bounds__(256) void hist_kernel(const int* __restrict__ edges)
{
    int i      = blockIdx.x * blockDim.x + threadIdx.x;
    int stride = gridDim.x * blockDim.x;
    const int4* ep = reinterpret_cast<const int4*>(edges);   // 2 edges per int4
    for (; i < N_EDGES / 2; i += stride) {
        const int4 e2 = ep[i];
        atomicAdd(&g_cnt[e2.y], 1);   // src of edge 2i
        atomicAdd(&g_cnt[e2.w], 1);   // src of edge 2i+1
    }
}

// ---------------- kernel 3: exclusive scan (single block) --------------------
__global__ __launch_bounds__(1024) void scan_kernel()
{
    __shared__ int sums[1024];
    const int T  = 1024;
    const int CH = (N_SRC + T - 1) / T;   // 98
    const int t  = threadIdx.x;
    const int beg = t * CH;
    const int end = (beg + CH < N_SRC) ? beg + CH : N_SRC;

    int mysum = 0;
    for (int i = beg; i < end; i++) mysum += g_cnt[i];
    sums[t] = mysum;
    __syncthreads();

    for (int o = 1; o < T; o <<= 1) {
        int v = (t >= o) ? sums[t - o] : 0;
        __syncthreads();
        sums[t] += v;
        __syncthreads();
    }

    int running = sums[t] - mysum;
    for (int i = beg; i < end; i++) {
        g_off[i] = running;
        g_cur[i] = running;
        running += g_cnt[i];
    }
    if (t == T - 1) g_off[N_SRC] = sums[T - 1];
}

// ---------------- kernel 4: reorder tgts into src buckets (2-edge ILP) -------
__global__ __launch_bounds__(256) void reorder_kernel(const int* __restrict__ edges)
{
    int i      = blockIdx.x * blockDim.x + threadIdx.x;
    int stride = gridDim.x * blockDim.x;
    const int4* ep = reinterpret_cast<const int4*>(edges);
    for (; i < N_EDGES / 2; i += stride) {
        const int4 e2 = ep[i];
        const int p0 = atomicAdd(&g_cur[e2.y], 1);
        const int p1 = atomicAdd(&g_cur[e2.w], 1);
        g_tgts[p0] = e2.x;
        g_tgts[p1] = e2.z;
    }
}

// ---------------- tensor-core GEMM helpers -----------------------------------
#define LDSM_X4(r0, r1, r2, r3, addr)                                          \
    asm volatile("ldmatrix.sync.aligned.m8n8.x4.shared.b16 {%0,%1,%2,%3},[%4];"\
                 : "=r"(r0), "=r"(r1), "=r"(r2), "=r"(r3) : "r"(addr))

#define LDSM_X4_T(r0, r1, r2, r3, addr)                                        \
    asm volatile("ldmatrix.sync.aligned.m8n8.x4.trans.shared.b16 {%0,%1,%2,%3},[%4];"\
                 : "=r"(r0), "=r"(r1), "=r"(r2), "=r"(r3) : "r"(addr))

#define MMA_BF16(c, a0, a1, a2, a3, b0, b1)                                    \
    asm volatile("mma.sync.aligned.m16n8k16.row.col.f32.bf16.bf16.f32 "        \
                 "{%0,%1,%2,%3},{%4,%5,%6,%7},{%8,%9},{%0,%1,%2,%3};"          \
                 : "+f"(c[0]), "+f"(c[1]), "+f"(c[2]), "+f"(c[3])              \
                 : "r"(a0), "r"(a1), "r"(a2), "r"(a3), "r"(b0), "r"(b1))

__device__ __forceinline__ void cvt_hilo4(float4 v, unsigned& hi0, unsigned& hi1,
                                          unsigned& lo0, unsigned& lo1)
{
    float f[4] = {v.x, v.y, v.z, v.w};
    unsigned short h[4], l[4];
#pragma unroll
    for (int i = 0; i < 4; i++) {
        __nv_bfloat16 hb = __float2bfloat16(f[i]);
        __nv_bfloat16 lb = __float2bfloat16(f[i] - __bfloat162float(hb));
        h[i] = __bfloat16_as_ushort(hb);
        l[i] = __bfloat16_as_ushort(lb);
    }
    hi0 = ((unsigned)h[1] << 16) | h[0];
    hi1 = ((unsigned)h[3] << 16) | h[2];
    lo0 = ((unsigned)l[1] << 16) | l[0];
    lo1 = ((unsigned)l[3] << 16) | l[2];
}

// ---------------- kernel 5: Wx = W @ x + b via bf16-split mma.sync -----------
#define A_PITCH 40    // 32 k + 8 pad (bf16)
#define B_PITCH 136   // 128 n + 8 pad (bf16)

__global__ __launch_bounds__(256, 2) void gemm_kernel(
    const float* __restrict__ x,      // (C, N_SRC)
    const float* __restrict__ W,      // (C_OUT, C_IN) row-major
    const float* __restrict__ b,      // (C,)
    const float* __restrict__ att,    // (C,)
    const float* __restrict__ alphap) // scalar
{
    __shared__ __align__(16) unsigned char sbuf[37888];
    __nv_bfloat16* As_hi = reinterpret_cast<__nv_bfloat16*>(sbuf);          // [128][40]
    __nv_bfloat16* As_lo = reinterpret_cast<__nv_bfloat16*>(sbuf + 10240);
    __nv_bfloat16* Bs_hi = reinterpret_cast<__nv_bfloat16*>(sbuf + 20480);  // [32][136]
    __nv_bfloat16* Bs_lo = reinterpret_cast<__nv_bfloat16*>(sbuf + 29184);
    __half*        S     = reinterpret_cast<__half*>(sbuf);                 // epilogue [128][136]
    __shared__ float bsh[128], ash[128];

    const int tid  = threadIdx.x;
    const int w    = tid >> 5;
    const int lane = tid & 31;
    const int nbase = blockIdx.x * 128;

    if (tid < 128) { bsh[tid] = b[tid]; ash[tid] = att[tid]; }
    const float alpha = __ldg(alphap);

    const unsigned saAhi = (unsigned)__cvta_generic_to_shared(As_hi);
    const unsigned saAlo = (unsigned)__cvta_generic_to_shared(As_lo);
    const unsigned saBhi = (unsigned)__cvta_generic_to_shared(Bs_hi);
    const unsigned saBlo = (unsigned)__cvta_generic_to_shared(Bs_lo);

    const int lrow  = lane & 15;
    const int lcol8 = (lane >> 4) * 8;

    float cc[8][2][4];
#pragma unroll
    for (int mt = 0; mt < 8; mt++)
#pragma unroll
        for (int nt = 0; nt < 2; nt++)
#pragma unroll
            for (int j = 0; j < 4; j++) cc[mt][nt][j] = 0.f;

    const int wn = w * 16;

    for (int kc = 0; kc < 4; kc++) {
        const int kbase = kc * 32;
        __syncthreads();

#pragma unroll
        for (int it = 0; it < 4; it++) {
            const int idx = it * 256 + tid;
            const int o   = idx >> 3;
            const int kq  = (idx & 7) * 4;
            float4 v = *reinterpret_cast<const float4*>(&W[(size_t)o * C + kbase + kq]);
            unsigned h0, h1, l0, l1;
            cvt_hilo4(v, h0, h1, l0, l1);
            unsigned* dh = reinterpret_cast<unsigned*>(&As_hi[o * A_PITCH + kq]);
            unsigned* dl = reinterpret_cast<unsigned*>(&As_lo[o * A_PITCH + kq]);
            dh[0] = h0; dh[1] = h1;
            dl[0] = l0; dl[1] = l1;
        }

#pragma unroll
        for (int it = 0; it < 4; it++) {
            const int r = it * 8 + w;
            const int n = nbase + lane * 4;
            float4 v = make_float4(0.f, 0.f, 0.f, 0.f);
            if (n < N_SRC)
                v = *reinterpret_cast<const float4*>(&x[(size_t)(kbase + r) * N_SRC + n]);
            unsigned h0, h1, l0, l1;
            cvt_hilo4(v, h0, h1, l0, l1);
            unsigned* dh = reinterpret_cast<unsigned*>(&Bs_hi[r * B_PITCH + lane * 4]);
            unsigned* dl = reinterpret_cast<unsigned*>(&Bs_lo[r * B_PITCH + lane * 4]);
            dh[0] = h0; dh[1] = h1;
            dl[0] = l0; dl[1] = l1;
        }
        __syncthreads();

#pragma unroll
        for (int ks = 0; ks < 2; ks++) {
            const int ko = ks * 16;
            const unsigned boff = (unsigned)(((ko + lrow) * B_PITCH + wn + lcol8) * 2);
            unsigned bh0, bh1, bh2, bh3, bl0, bl1, bl2, bl3;
            LDSM_X4_T(bh0, bh1, bh2, bh3, saBhi + boff);
            LDSM_X4_T(bl0, bl1, bl2, bl3, saBlo + boff);

#pragma unroll
            for (int mt = 0; mt < 8; mt++) {
                const unsigned aoff =
                    (unsigned)(((mt * 16 + lrow) * A_PITCH + ko + lcol8) * 2);
                unsigned ah0, ah1, ah2, ah3, al0, al1, al2, al3;
                LDSM_X4(ah0, ah1, ah2, ah3, saAhi + aoff);
                LDSM_X4(al0, al1, al2, al3, saAlo + aoff);

                MMA_BF16(cc[mt][0], ah0, ah1, ah2, ah3, bh0, bh1);
                MMA_BF16(cc[mt][1], ah0, ah1, ah2, ah3, bh2, bh3);
                MMA_BF16(cc[mt][0], ah0, ah1, ah2, ah3, bl0, bl1);
                MMA_BF16(cc[mt][1], ah0, ah1, ah2, ah3, bl2, bl3);
                MMA_BF16(cc[mt][0], al0, al1, al2, al3, bh0, bh1);
                MMA_BF16(cc[mt][1], al0, al1, al2, al3, bh2, bh3);
            }
        }
    }

    __syncthreads();

    const int g  = lane >> 2;
    const int tg = lane & 3;
    float part[2][2] = {{0.f, 0.f}, {0.f, 0.f}};

#pragma unroll
    for (int mt = 0; mt < 8; mt++) {
        const int o0 = mt * 16 + g;
        const int o1 = o0 + 8;
        const float b0 = bsh[o0], b1 = bsh[o1];
        const float a0 = ash[o0], a1 = ash[o1];
#pragma unroll
        for (int nt = 0; nt < 2; nt++) {
            const float c0 = cc[mt][nt][0] + b0;
            const float c1 = cc[mt][nt][1] + b0;
            const float c2 = cc[mt][nt][2] + b1;
            const float c3 = cc[mt][nt][3] + b1;
            const int n0 = wn + nt * 8 + tg * 2;
            S[n0 * B_PITCH + o0]       = __float2half(c0);
            S[(n0 + 1) * B_PITCH + o0] = __float2half(c1);
            S[n0 * B_PITCH + o1]       = __float2half(c2);
            S[(n0 + 1) * B_PITCH + o1] = __float2half(c3);
            part[nt][0] += a0 * c0 + a1 * c2;
            part[nt][1] += a0 * c1 + a1 * c3;
        }
    }

#pragma unroll
    for (int m = 4; m < 32; m <<= 1)
#pragma unroll
        for (int nt = 0; nt < 2; nt++)
#pragma unroll
            for (int j = 0; j < 2; j++)
                part[nt][j] += __shfl_xor_sync(0xFFFFFFFFu, part[nt][j], m);

    if (lane < 4) {
#pragma unroll
        for (int nt = 0; nt < 2; nt++) {
#pragma unroll
            for (int j = 0; j < 2; j++) {
                const int n = nbase + wn + nt * 8 + lane * 2 + j;
                if (n < N_SRC) {
                    float a = part[nt][j];
                    a = (a >= 0.f) ? a : alpha * a;
                    g_expa[n] = __expf(a);
                }
            }
        }
    }
    __syncthreads();

    for (int idx = tid; idx < 128 * 16; idx += 256) {
        const int n  = idx >> 4;
        const int c8 = (idx & 15) * 8;
        const int gn = nbase + n;
        if (gn < N_SRC)
            *reinterpret_cast<uint4*>(&g_Wxh[(size_t)gn * C + c8]) =
                *reinterpret_cast<const uint4*>(&S[n * B_PITCH + c8]);
    }
}

// ---------------- kernel 6: src-grouped scatter (1 warp per src) -------------
// Row read ONCE per src (256B coalesced), scaled by expa once; then one
// red.add.v4 per out-edge. tgt loads are warp-uniform (broadcast, 1 sector).
__global__ __launch_bounds__(256) void scatter2_kernel()
{
    const int s    = blockIdx.x * 8 + (threadIdx.x >> 5);
    const int lane = threadIdx.x & 31;

    const float ex = g_expa[s];

    const uint2 h = *reinterpret_cast<const uint2*>(&g_Wxh[(size_t)s * C + lane * 4]);
    const float2 f0 = __half22float2(*reinterpret_cast<const __half2*>(&h.x));
    const float2 f1 = __half22float2(*reinterpret_cast<const __half2*>(&h.y));
    const float vx = f0.x * ex, vy = f0.y * ex, vz = f1.x * ex, vw = f1.y * ex;

    const int beg = g_off[s];
    const int end = g_off[s + 1];

#pragma unroll 4
    for (int j = beg; j < end; j++) {
        const int tgt = __ldg(&g_tgts[j]);       // uniform across warp
        float* np = &g_num[(size_t)tgt * C + lane * 4];
        asm volatile("red.global.add.v4.f32 [%0], {%1, %2, %3, %4};"
                     :: "l"(np), "f"(vx), "f"(vy), "f"(vz), "f"(vw)
                     : "memory");
        if (lane == 0)
            atomicAdd(&g_den[tgt], ex);
    }
}

// ---------------- kernel 7: normalize + transpose to (C, N_OUT) --------------
__global__ __launch_bounds__(256) void finalize_kernel(float* __restrict__ out)
{
    __shared__ float tile[32][33];
    __shared__ float dsh[32];

    const int tx = threadIdx.x;
    const int ty = threadIdx.y;
    const int n0 = blockIdx.x * 32;
    const int o0 = blockIdx.y * 32;

    if (ty == 0) {
        const int n = n0 + tx;
        float d = (n < N_OUT) ? g_den[n] : 1.f;
        dsh[tx] = (d == 0.f) ? 1.f : d;
    }

#pragma unroll
    for (int r = 0; r < 4; r++) {
        const int n = n0 + ty + r * 8;
        if (n < N_OUT)
            tile[ty + r * 8][tx] = g_num[(size_t)n * C + o0 + tx];
    }
    __syncthreads();

    const float rd = 1.f / dsh[tx];
#pragma unroll
    for (int r = 0; r < 4; r++) {
        const int o = o0 + ty + r * 8;
        const int n = n0 + tx;
        if (n < N_OUT)
            out[(size_t)o * N_OUT + n] = tile[tx][ty + r * 8] * rd;
    }
}

// ---------------- launch ------------------------------------------------------
extern "C" void kernel_launch(void* const* d_in, const int* in_sizes, int n_in,
                              void* d_out, int out_size)
{
    const float* x     = (const float*)d_in[0];
    const int*   edges = (const int*)  d_in[1];
    const float* W     = (const float*)d_in[2];
    const float* b     = (const float*)d_in[3];
    const float* att   = (const float*)d_in[4];
    const float* alpha = (const float*)d_in[5];
    float* out = (float*)d_out;

    zero_kernel<<<2048, 256>>>();
    hist_kernel<<<1184, 256>>>(edges);
    scan_kernel<<<1, 1024>>>();
    reorder_kernel<<<1184, 256>>>(edges);
    gemm_kernel<<<(N_SRC + 127) / 128, 256>>>(x, W, b, att, alpha);
    scatter2_kernel<<<N_SRC / 8, 256>>>();
    dim3 fgrid((N_OUT + 31) / 32, C / 32);
    finalize_kernel<<<fgrid, dim3(32, 8)>>>(out);
}

// round 7
// speedup vs baseline: 1.6111x; 1.6111x over previous
#include <cuda_runtime.h>
#include <cuda_fp16.h>
#include <cuda_bf16.h>
#include <cstdint>
#include <cstddef>

#define N_SRC   100000
#define N_OUT   100000
#define N_EDGES 1600000
#define C       128

// ---------------- scratch (device globals; no allocation allowed) ------------
__device__ __half g_Wxh[(size_t)N_SRC * C];  // node-major fp16 Wx, 25.6 MB
__device__ float  g_num[(size_t)N_OUT * C];  // node-major accumulators, 51.2 MB
__device__ float  g_expa[N_SRC];
__device__ float  g_den[N_OUT];

// ---------------- tensor-core GEMM helpers -----------------------------------
#define LDSM_X4(r0, r1, r2, r3, addr)                                          \
    asm volatile("ldmatrix.sync.aligned.m8n8.x4.shared.b16 {%0,%1,%2,%3},[%4];"\
                 : "=r"(r0), "=r"(r1), "=r"(r2), "=r"(r3) : "r"(addr))

#define LDSM_X4_T(r0, r1, r2, r3, addr)                                        \
    asm volatile("ldmatrix.sync.aligned.m8n8.x4.trans.shared.b16 {%0,%1,%2,%3},[%4];"\
                 : "=r"(r0), "=r"(r1), "=r"(r2), "=r"(r3) : "r"(addr))

#define MMA_BF16(c, a0, a1, a2, a3, b0, b1)                                    \
    asm volatile("mma.sync.aligned.m16n8k16.row.col.f32.bf16.bf16.f32 "        \
                 "{%0,%1,%2,%3},{%4,%5,%6,%7},{%8,%9},{%0,%1,%2,%3};"          \
                 : "+f"(c[0]), "+f"(c[1]), "+f"(c[2]), "+f"(c[3])              \
                 : "r"(a0), "r"(a1), "r"(a2), "r"(a3), "r"(b0), "r"(b1))

__device__ __forceinline__ void cvt_hilo4(float4 v, unsigned& hi0, unsigned& hi1,
                                          unsigned& lo0, unsigned& lo1)
{
    float f[4] = {v.x, v.y, v.z, v.w};
    unsigned short h[4], l[4];
#pragma unroll
    for (int i = 0; i < 4; i++) {
        __nv_bfloat16 hb = __float2bfloat16(f[i]);
        __nv_bfloat16 lb = __float2bfloat16(f[i] - __bfloat162float(hb));
        h[i] = __bfloat16_as_ushort(hb);
        l[i] = __bfloat16_as_ushort(lb);
    }
    hi0 = ((unsigned)h[1] << 16) | h[0];
    hi1 = ((unsigned)h[3] << 16) | h[2];
    lo0 = ((unsigned)l[1] << 16) | l[0];
    lo1 = ((unsigned)l[3] << 16) | l[2];
}

// ---------------- kernel 1: Wx = W @ x + b via bf16-split mma.sync -----------
// Prologue also zeroes g_num / g_den (DRAM stores hidden under compute).
#define A_PITCH 40    // 32 k + 8 pad (bf16)
#define B_PITCH 136   // 128 n + 8 pad (bf16)
#define GEMM_BLOCKS ((N_SRC + 127) / 128)     // 782

__global__ __launch_bounds__(256, 2) void gemm_kernel(
    const float* __restrict__ x,      // (C, N_SRC)
    const float* __restrict__ W,      // (C_OUT, C_IN) row-major
    const float* __restrict__ b,      // (C,)
    const float* __restrict__ att,    // (C,)
    const float* __restrict__ alphap) // scalar
{
    __shared__ __align__(16) unsigned char sbuf[37888];
    __nv_bfloat16* As_hi = reinterpret_cast<__nv_bfloat16*>(sbuf);          // [128][40]
    __nv_bfloat16* As_lo = reinterpret_cast<__nv_bfloat16*>(sbuf + 10240);
    __nv_bfloat16* Bs_hi = reinterpret_cast<__nv_bfloat16*>(sbuf + 20480);  // [32][136]
    __nv_bfloat16* Bs_lo = reinterpret_cast<__nv_bfloat16*>(sbuf + 29184);
    __half*        S     = reinterpret_cast<__half*>(sbuf);                 // epilogue [128][136]
    __shared__ float bsh[128], ash[128];

    const int tid  = threadIdx.x;
    const int w    = tid >> 5;
    const int lane = tid & 31;
    const int nbase = blockIdx.x * 128;

    // ---- fused zeroing of num/den (stores fly while we compute) ----
    {
        const unsigned gi  = blockIdx.x * 256 + tid;
        const unsigned gst = GEMM_BLOCKS * 256;
        float4* np = reinterpret_cast<float4*>(g_num);
        const unsigned n4 = (unsigned)((size_t)N_OUT * C / 4);
        for (unsigned k = gi; k < n4; k += gst)
            np[k] = make_float4(0.f, 0.f, 0.f, 0.f);
        for (unsigned k = gi; k < N_OUT; k += gst)
            g_den[k] = 0.f;
    }

    if (tid < 128) { bsh[tid] = b[tid]; ash[tid] = att[tid]; }
    const float alpha = __ldg(alphap);

    const unsigned saAhi = (unsigned)__cvta_generic_to_shared(As_hi);
    const unsigned saAlo = (unsigned)__cvta_generic_to_shared(As_lo);
    const unsigned saBhi = (unsigned)__cvta_generic_to_shared(Bs_hi);
    const unsigned saBlo = (unsigned)__cvta_generic_to_shared(Bs_lo);

    const int lrow  = lane & 15;
    const int lcol8 = (lane >> 4) * 8;

    float cc[8][2][4];
#pragma unroll
    for (int mt = 0; mt < 8; mt++)
#pragma unroll
        for (int nt = 0; nt < 2; nt++)
#pragma unroll
            for (int j = 0; j < 4; j++) cc[mt][nt][j] = 0.f;

    const int wn = w * 16;

    for (int kc = 0; kc < 4; kc++) {
        const int kbase = kc * 32;
        __syncthreads();

#pragma unroll
        for (int it = 0; it < 4; it++) {
            const int idx = it * 256 + tid;
            const int o   = idx >> 3;
            const int kq  = (idx & 7) * 4;
            float4 v = *reinterpret_cast<const float4*>(&W[(size_t)o * C + kbase + kq]);
            unsigned h0, h1, l0, l1;
            cvt_hilo4(v, h0, h1, l0, l1);
            unsigned* dh = reinterpret_cast<unsigned*>(&As_hi[o * A_PITCH + kq]);
            unsigned* dl = reinterpret_cast<unsigned*>(&As_lo[o * A_PITCH + kq]);
            dh[0] = h0; dh[1] = h1;
            dl[0] = l0; dl[1] = l1;
        }

#pragma unroll
        for (int it = 0; it < 4; it++) {
            const int r = it * 8 + w;
            const int n = nbase + lane * 4;
            float4 v = make_float4(0.f, 0.f, 0.f, 0.f);
            if (n < N_SRC)
                v = *reinterpret_cast<const float4*>(&x[(size_t)(kbase + r) * N_SRC + n]);
            unsigned h0, h1, l0, l1;
            cvt_hilo4(v, h0, h1, l0, l1);
            unsigned* dh = reinterpret_cast<unsigned*>(&Bs_hi[r * B_PITCH + lane * 4]);
            unsigned* dl = reinterpret_cast<unsigned*>(&Bs_lo[r * B_PITCH + lane * 4]);
            dh[0] = h0; dh[1] = h1;
            dl[0] = l0; dl[1] = l1;
        }
        __syncthreads();

#pragma unroll
        for (int ks = 0; ks < 2; ks++) {
            const int ko = ks * 16;
            const unsigned boff = (unsigned)(((ko + lrow) * B_PITCH + wn + lcol8) * 2);
            unsigned bh0, bh1, bh2, bh3, bl0, bl1, bl2, bl3;
            LDSM_X4_T(bh0, bh1, bh2, bh3, saBhi + boff);
            LDSM_X4_T(bl0, bl1, bl2, bl3, saBlo + boff);

#pragma unroll
            for (int mt = 0; mt < 8; mt++) {
                const unsigned aoff =
                    (unsigned)(((mt * 16 + lrow) * A_PITCH + ko + lcol8) * 2);
                unsigned ah0, ah1, ah2, ah3, al0, al1, al2, al3;
                LDSM_X4(ah0, ah1, ah2, ah3, saAhi + aoff);
                LDSM_X4(al0, al1, al2, al3, saAlo + aoff);

                MMA_BF16(cc[mt][0], ah0, ah1, ah2, ah3, bh0, bh1);
                MMA_BF16(cc[mt][1], ah0, ah1, ah2, ah3, bh2, bh3);
                MMA_BF16(cc[mt][0], ah0, ah1, ah2, ah3, bl0, bl1);
                MMA_BF16(cc[mt][1], ah0, ah1, ah2, ah3, bl2, bl3);
                MMA_BF16(cc[mt][0], al0, al1, al2, al3, bh0, bh1);
                MMA_BF16(cc[mt][1], al0, al1, al2, al3, bh2, bh3);
            }
        }
    }

    __syncthreads();

    const int g  = lane >> 2;
    const int tg = lane & 3;
    float part[2][2] = {{0.f, 0.f}, {0.f, 0.f}};

#pragma unroll
    for (int mt = 0; mt < 8; mt++) {
        const int o0 = mt * 16 + g;
        const int o1 = o0 + 8;
        const float b0 = bsh[o0], b1 = bsh[o1];
        const float a0 = ash[o0], a1 = ash[o1];
#pragma unroll
        for (int nt = 0; nt < 2; nt++) {
            const float c0 = cc[mt][nt][0] + b0;
            const float c1 = cc[mt][nt][1] + b0;
            const float c2 = cc[mt][nt][2] + b1;
            const float c3 = cc[mt][nt][3] + b1;
            const int n0 = wn + nt * 8 + tg * 2;
            S[n0 * B_PITCH + o0]       = __float2half(c0);
            S[(n0 + 1) * B_PITCH + o0] = __float2half(c1);
            S[n0 * B_PITCH + o1]       = __float2half(c2);
            S[(n0 + 1) * B_PITCH + o1] = __float2half(c3);
            part[nt][0] += a0 * c0 + a1 * c2;
            part[nt][1] += a0 * c1 + a1 * c3;
        }
    }

#pragma unroll
    for (int m = 4; m < 32; m <<= 1)
#pragma unroll
        for (int nt = 0; nt < 2; nt++)
#pragma unroll
            for (int j = 0; j < 2; j++)
                part[nt][j] += __shfl_xor_sync(0xFFFFFFFFu, part[nt][j], m);

    if (lane < 4) {
#pragma unroll
        for (int nt = 0; nt < 2; nt++) {
#pragma unroll
            for (int j = 0; j < 2; j++) {
                const int n = nbase + wn + nt * 8 + lane * 2 + j;
                if (n < N_SRC) {
                    float a = part[nt][j];
                    a = (a >= 0.f) ? a : alpha * a;
                    g_expa[n] = __expf(a);
                }
            }
        }
    }
    __syncthreads();

    for (int idx = tid; idx < 128 * 16; idx += 256) {
        const int n  = idx >> 4;
        const int c8 = (idx & 15) * 8;
        const int gn = nbase + n;
        if (gn < N_SRC)
            *reinterpret_cast<uint4*>(&g_Wxh[(size_t)gn * C + c8]) =
                *reinterpret_cast<const uint4*>(&S[n * B_PITCH + c8]);
    }
}

// ---------------- kernel 2: edge scatter (1 warp per edge, fp16 gather) ------
__global__ __launch_bounds__(256) void scatter_kernel(const int* __restrict__ edges)
{
    const int e    = blockIdx.x * 8 + (threadIdx.x >> 5);
    const int lane = threadIdx.x & 31;

    const int2 ts = reinterpret_cast<const int2*>(edges)[e];
    const int tgt = ts.x;
    const int src = ts.y;

    const float ex = __ldg((const float*)&g_expa[src]);

    const uint2 h = *reinterpret_cast<const uint2*>(&g_Wxh[(size_t)src * C + lane * 4]);
    const float2 f0 = __half22float2(*reinterpret_cast<const __half2*>(&h.x));
    const float2 f1 = __half22float2(*reinterpret_cast<const __half2*>(&h.y));

    float4 v;
    v.x = f0.x * ex; v.y = f0.y * ex;
    v.z = f1.x * ex; v.w = f1.y * ex;

    float* np = &g_num[(size_t)tgt * C + lane * 4];
    asm volatile("red.global.add.v4.f32 [%0], {%1, %2, %3, %4};"
                 :: "l"(np), "f"(v.x), "f"(v.y), "f"(v.z), "f"(v.w)
                 : "memory");

    if (lane == 0)
        atomicAdd(&g_den[tgt], ex);
}

// ---------------- kernel 3: normalize + transpose, 32 n x 128 o per block ----
__global__ __launch_bounds__(256) void finalize_kernel(float* __restrict__ out)
{
    __shared__ float tile[32][129];
    __shared__ float dsh[32];

    const int tid  = threadIdx.x;
    const int lane = tid & 31;
    const int w    = tid >> 5;
    const int n0   = blockIdx.x * 32;

    if (tid < 32) {
        float d = g_den[n0 + tid];
        dsh[tid] = (d == 0.f) ? 1.f : d;
    }

    // load: 32 rows x 128 floats = 1024 float4, 4 per thread (coalesced)
#pragma unroll
    for (int it = 0; it < 4; it++) {
        const int idx = it * 256 + tid;       // 0..1023
        const int n   = idx >> 5;             // row 0..31
        const int o4  = (idx & 31) * 4;       // col group
        const float4 v =
            *reinterpret_cast<const float4*>(&g_num[(size_t)(n0 + n) * C + o4]);
        tile[n][o4 + 0] = v.x;
        tile[n][o4 + 1] = v.y;
        tile[n][o4 + 2] = v.z;
        tile[n][o4 + 3] = v.w;
    }
    __syncthreads();

    const float rd = 1.f / dsh[lane];
    // write transposed: warp w covers o = w, w+8, ..., w+120 (16 rows)
#pragma unroll
    for (int r = 0; r < 16; r++) {
        const int o = w + r * 8;
        out[(size_t)o * N_OUT + n0 + lane] = tile[lane][o] * rd;
    }
}

// ---------------- launch ------------------------------------------------------
extern "C" void kernel_launch(void* const* d_in, const int* in_sizes, int n_in,
                              void* d_out, int out_size)
{
    const float* x     = (const float*)d_in[0];
    const int*   edges = (const int*)  d_in[1];
    const float* W     = (const float*)d_in[2];
    const float* b     = (const float*)d_in[3];
    const float* att   = (const float*)d_in[4];
    const float* alpha = (const float*)d_in[5];
    float* out = (float*)d_out;

    gemm_kernel<<<GEMM_BLOCKS, 256>>>(x, W, b, att, alpha);
    scatter_kernel<<<N_EDGES / 8, 256>>>(edges);
    finalize_kernel<<<N_OUT / 32, 256>>>(out);
}

// round 9
// speedup vs baseline: 1.6342x; 1.0144x over previous
#include <cuda_runtime.h>
#include <cuda_fp16.h>
#include <cuda_bf16.h>
#include <cstdint>
#include <cstddef>

#define N_SRC   100000
#define N_OUT   100000
#define N_EDGES 1600000
#define C       128

// ---------------- scratch (device globals; no allocation allowed) ------------
__device__ __half        g_Wxh[(size_t)N_SRC * C];  // node-major fp16 Wx
__device__ float         g_num[(size_t)N_OUT * C];  // accumulators
__device__ float         g_expa[N_SRC];
__device__ float         g_den[N_OUT];
__device__ __nv_bfloat16 g_Whi[C * C];              // W bf16 hi, row-major [o][k]
__device__ __nv_bfloat16 g_Wlo[C * C];              // W bf16 lo

// ---------------- kernel 0: one-time W split to bf16 hi/lo -------------------
__global__ void wcvt_kernel(const float* __restrict__ W)
{
    const int i = blockIdx.x * 256 + threadIdx.x;   // 0..16383
    const float f = W[i];
    const __nv_bfloat16 hb = __float2bfloat16(f);
    g_Whi[i] = hb;
    g_Wlo[i] = __float2bfloat16(f - __bfloat162float(hb));
}

// ---------------- tensor-core GEMM helpers -----------------------------------
#define LDSM_X4(r0, r1, r2, r3, addr)                                          \
    asm volatile("ldmatrix.sync.aligned.m8n8.x4.shared.b16 {%0,%1,%2,%3},[%4];"\
                 : "=r"(r0), "=r"(r1), "=r"(r2), "=r"(r3) : "r"(addr))

#define LDSM_X4_T(r0, r1, r2, r3, addr)                                        \
    asm volatile("ldmatrix.sync.aligned.m8n8.x4.trans.shared.b16 {%0,%1,%2,%3},[%4];"\
                 : "=r"(r0), "=r"(r1), "=r"(r2), "=r"(r3) : "r"(addr))

#define MMA_BF16(c, a0, a1, a2, a3, b0, b1)                                    \
    asm volatile("mma.sync.aligned.m16n8k16.row.col.f32.bf16.bf16.f32 "        \
                 "{%0,%1,%2,%3},{%4,%5,%6,%7},{%8,%9},{%0,%1,%2,%3};"          \
                 : "+f"(c[0]), "+f"(c[1]), "+f"(c[2]), "+f"(c[3])              \
                 : "r"(a0), "r"(a1), "r"(a2), "r"(a3), "r"(b0), "r"(b1))

__device__ __forceinline__ void cvt_hilo4(float4 v, unsigned& hi0, unsigned& hi1,
                                          unsigned& lo0, unsigned& lo1)
{
    float f[4] = {v.x, v.y, v.z, v.w};
    unsigned short h[4], l[4];
#pragma unroll
    for (int i = 0; i < 4; i++) {
        __nv_bfloat16 hb = __float2bfloat16(f[i]);
        __nv_bfloat16 lb = __float2bfloat16(f[i] - __bfloat162float(hb));
        h[i] = __bfloat16_as_ushort(hb);
        l[i] = __bfloat16_as_ushort(lb);
    }
    hi0 = ((unsigned)h[1] << 16) | h[0];
    hi1 = ((unsigned)h[3] << 16) | h[2];
    lo0 = ((unsigned)l[1] << 16) | l[0];
    lo1 = ((unsigned)l[3] << 16) | l[2];
}

// ---------------- kernel 1: Wx = W @ x + b via bf16-split mma.sync -----------
// Block 128 n x 128 o; warp grid 4(n) x 2(o): warp owns 32 n x 64 o.
// Per k16 step: 12 LDSM.x4 for 48 MMAs (was 18). W staged pre-split from gmem.
#define A_PITCH 40    // 32 k + 8 pad (bf16)
#define B_PITCH 136   // 128 n + 8 pad (bf16)
#define GEMM_BLOCKS ((N_SRC + 127) / 128)     // 782

__global__ __launch_bounds__(256, 2) void gemm_kernel(
    const float* __restrict__ x,      // (C, N_SRC)
    const float* __restrict__ b,      // (C,)
    const float* __restrict__ att,    // (C,)
    const float* __restrict__ alphap) // scalar
{
    __shared__ __align__(16) unsigned char sbuf[37888];
    __nv_bfloat16* As_hi = reinterpret_cast<__nv_bfloat16*>(sbuf);          // [128][40]
    __nv_bfloat16* As_lo = reinterpret_cast<__nv_bfloat16*>(sbuf + 10240);
    __nv_bfloat16* Bs_hi = reinterpret_cast<__nv_bfloat16*>(sbuf + 20480);  // [32][136]
    __nv_bfloat16* Bs_lo = reinterpret_cast<__nv_bfloat16*>(sbuf + 29184);
    __half*        S     = reinterpret_cast<__half*>(sbuf);                 // epilogue [128][136]
    __shared__ float bsh[128], ash[128], sdot[128];

    const int tid  = threadIdx.x;
    const int w    = tid >> 5;
    const int lane = tid & 31;
    const int nbase = blockIdx.x * 128;

    // ---- fused zeroing of num/den ----
    {
        const unsigned gi  = blockIdx.x * 256 + tid;
        const unsigned gst = GEMM_BLOCKS * 256;
        float4* np = reinterpret_cast<float4*>(g_num);
        const unsigned n4 = (unsigned)((size_t)N_OUT * C / 4);
        for (unsigned k = gi; k < n4; k += gst)
            np[k] = make_float4(0.f, 0.f, 0.f, 0.f);
        for (unsigned k = gi; k < N_OUT; k += gst)
            g_den[k] = 0.f;
    }

    if (tid < 128) { bsh[tid] = b[tid]; ash[tid] = att[tid]; sdot[tid] = 0.f; }
    const float alpha = __ldg(alphap);

    const unsigned saAhi = (unsigned)__cvta_generic_to_shared(As_hi);
    const unsigned saAlo = (unsigned)__cvta_generic_to_shared(As_lo);
    const unsigned saBhi = (unsigned)__cvta_generic_to_shared(Bs_hi);
    const unsigned saBlo = (unsigned)__cvta_generic_to_shared(Bs_lo);

    const int lrow  = lane & 15;
    const int lcol8 = (lane >> 4) * 8;

    const int ow = w & 1;        // o-half: 64 o
    const int nw = w >> 1;       // n-quarter: 32 n
    const int nb = nw * 32;
    const int ob = ow * 64;

    float cc[4][4][4];
#pragma unroll
    for (int mt = 0; mt < 4; mt++)
#pragma unroll
        for (int nt = 0; nt < 4; nt++)
#pragma unroll
            for (int j = 0; j < 4; j++) cc[mt][nt][j] = 0.f;

    for (int kc = 0; kc < 4; kc++) {
        const int kbase = kc * 32;
        __syncthreads();

        // ---- W chunk: straight bf16 copy gmem -> smem (no conversion) ----
#pragma unroll
        for (int it = 0; it < 2; it++) {
            const int idx = it * 256 + tid;       // 0..511 uint4s per array
            const int o   = idx >> 2;
            const int kq  = (idx & 3) * 8;
            *reinterpret_cast<uint4*>(&As_hi[o * A_PITCH + kq]) =
                *reinterpret_cast<const uint4*>(&g_Whi[o * C + kbase + kq]);
            *reinterpret_cast<uint4*>(&As_lo[o * A_PITCH + kq]) =
                *reinterpret_cast<const uint4*>(&g_Wlo[o * C + kbase + kq]);
        }

        // ---- x chunk: load fp32, split to hi/lo ----
#pragma unroll
        for (int it = 0; it < 4; it++) {
            const int r = it * 8 + w;
            const int n = nbase + lane * 4;
            float4 v = make_float4(0.f, 0.f, 0.f, 0.f);
            if (n < N_SRC)
                v = *reinterpret_cast<const float4*>(&x[(size_t)(kbase + r) * N_SRC + n]);
            unsigned h0, h1, l0, l1;
            cvt_hilo4(v, h0, h1, l0, l1);
            unsigned* dh = reinterpret_cast<unsigned*>(&Bs_hi[r * B_PITCH + lane * 4]);
            unsigned* dl = reinterpret_cast<unsigned*>(&Bs_lo[r * B_PITCH + lane * 4]);
            dh[0] = h0; dh[1] = h1;
            dl[0] = l0; dl[1] = l1;
        }
        __syncthreads();

#pragma unroll
        for (int ks = 0; ks < 2; ks++) {
            const int ko = ks * 16;
            const unsigned boff0 = (unsigned)(((ko + lrow) * B_PITCH + nb + lcol8) * 2);
            const unsigned boff1 = (unsigned)(((ko + lrow) * B_PITCH + nb + 16 + lcol8) * 2);
            unsigned bh[8], bl[8];
            LDSM_X4_T(bh[0], bh[1], bh[2], bh[3], saBhi + boff0);
            LDSM_X4_T(bh[4], bh[5], bh[6], bh[7], saBhi + boff1);
            LDSM_X4_T(bl[0], bl[1], bl[2], bl[3], saBlo + boff0);
            LDSM_X4_T(bl[4], bl[5], bl[6], bl[7], saBlo + boff1);

#pragma unroll
            for (int mt = 0; mt < 4; mt++) {
                const unsigned aoff =
                    (unsigned)(((ob + mt * 16 + lrow) * A_PITCH + ko + lcol8) * 2);
                unsigned ah0, ah1, ah2, ah3, al0, al1, al2, al3;
                LDSM_X4(ah0, ah1, ah2, ah3, saAhi + aoff);
                LDSM_X4(al0, al1, al2, al3, saAlo + aoff);

#pragma unroll
                for (int nt = 0; nt < 4; nt++) {
                    MMA_BF16(cc[mt][nt], ah0, ah1, ah2, ah3, bh[2*nt], bh[2*nt+1]);
                    MMA_BF16(cc[mt][nt], ah0, ah1, ah2, ah3, bl[2*nt], bl[2*nt+1]);
                    MMA_BF16(cc[mt][nt], al0, al1, al2, al3, bh[2*nt], bh[2*nt+1]);
                }
            }
        }
    }

    __syncthreads();   // mainloop smem dead; S may alias it

    // ---- epilogue: bias, att-dot partials, fp16 staging ----
    const int g  = lane >> 2;
    const int tg = lane & 3;
    float part[4][2];
#pragma unroll
    for (int nt = 0; nt < 4; nt++) { part[nt][0] = 0.f; part[nt][1] = 0.f; }

#pragma unroll
    for (int mt = 0; mt < 4; mt++) {
        const int o0 = ob + mt * 16 + g;
        const int o1 = o0 + 8;
        const float b0 = bsh[o0], b1 = bsh[o1];
        const float a0 = ash[o0], a1 = ash[o1];
#pragma unroll
        for (int nt = 0; nt < 4; nt++) {
            const float c0 = cc[mt][nt][0] + b0;
            const float c1 = cc[mt][nt][1] + b0;
            const float c2 = cc[mt][nt][2] + b1;
            const float c3 = cc[mt][nt][3] + b1;
            const int n0 = nb + nt * 8 + tg * 2;
            S[n0 * B_PITCH + o0]       = __float2half(c0);
            S[(n0 + 1) * B_PITCH + o0] = __float2half(c1);
            S[n0 * B_PITCH + o1]       = __float2half(c2);
            S[(n0 + 1) * B_PITCH + o1] = __float2half(c3);
            part[nt][0] += a0 * c0 + a1 * c2;
            part[nt][1] += a0 * c1 + a1 * c3;
        }
    }

    // reduce over g (lane bits 2-4), preserving tg
#pragma unroll
    for (int m = 4; m < 32; m <<= 1)
#pragma unroll
        for (int nt = 0; nt < 4; nt++)
#pragma unroll
            for (int j = 0; j < 2; j++)
                part[nt][j] += __shfl_xor_sync(0xFFFFFFFFu, part[nt][j], m);

    if (lane < 4) {
#pragma unroll
        for (int nt = 0; nt < 4; nt++)
#pragma unroll
            for (int j = 0; j < 2; j++)
                atomicAdd(&sdot[nb + nt * 8 + lane * 2 + j], part[nt][j]);
    }
    __syncthreads();

    if (tid < 128) {
        const int n = nbase + tid;
        if (n < N_SRC) {
            float a = sdot[tid];
            a = (a >= 0.f) ? a : alpha * a;
            g_expa[n] = __expf(a);
        }
    }

    // ---- coalesced fp16 Wx store ----
    for (int idx = tid; idx < 128 * 16; idx += 256) {
        const int n  = idx >> 4;
        const int c8 = (idx & 15) * 8;
        const int gn = nbase + n;
        if (gn < N_SRC)
            *reinterpret_cast<uint4*>(&g_Wxh[(size_t)gn * C + c8]) =
                *reinterpret_cast<const uint4*>(&S[n * B_PITCH + c8]);
    }
}

// ---------------- kernel 2: edge scatter (1 warp per edge, fp16 gather) ------
__global__ __launch_bounds__(256) void scatter_kernel(const int* __restrict__ edges)
{
    const int e    = blockIdx.x * 8 + (threadIdx.x >> 5);
    const int lane = threadIdx.x & 31;

    const int2 ts = reinterpret_cast<const int2*>(edges)[e];
    const int tgt = ts.x;
    const int src = ts.y;

    const float ex = __ldg((const float*)&g_expa[src]);

    const uint2 h = *reinterpret_cast<const uint2*>(&g_Wxh[(size_t)src * C + lane * 4]);
    const float2 f0 = __half22float2(*reinterpret_cast<const __half2*>(&h.x));
    const float2 f1 = __half22float2(*reinterpret_cast<const __half2*>(&h.y));

    float4 v;
    v.x = f0.x * ex; v.y = f0.y * ex;
    v.z = f1.x * ex; v.w = f1.y * ex;

    float* np = &g_num[(size_t)tgt * C + lane * 4];
    asm volatile("red.global.add.v4.f32 [%0], {%1, %2, %3, %4};"
                 :: "l"(np), "f"(v.x), "f"(v.y), "f"(v.z), "f"(v.w)
                 : "memory");

    if (lane == 0)
        atomicAdd(&g_den[tgt], ex);
}

// ---------------- kernel 3: normalize + transpose, 32 n x 128 o per block ----
__global__ __launch_bounds__(256) void finalize_kernel(float* __restrict__ out)
{
    __shared__ float tile[32][129];
    __shared__ float dsh[32];

    const int tid  = threadIdx.x;
    const int lane = tid & 31;
    const int w    = tid >> 5;
    const int n0   = blockIdx.x * 32;

    if (tid < 32) {
        float d = g_den[n0 + tid];
        dsh[tid] = (d == 0.f) ? 1.f : d;
    }

#pragma unroll
    for (int it = 0; it < 4; it++) {
        const int idx = it * 256 + tid;
        const int n   = idx >> 5;
        const int o4  = (idx & 31) * 4;
        const float4 v =
            *reinterpret_cast<const float4*>(&g_num[(size_t)(n0 + n) * C + o4]);
        tile[n][o4 + 0] = v.x;
        tile[n][o4 + 1] = v.y;
        tile[n][o4 + 2] = v.z;
        tile[n][o4 + 3] = v.w;
    }
    __syncthreads();

    const float rd = 1.f / dsh[lane];
#pragma unroll
    for (int r = 0; r < 16; r++) {
        const int o = w + r * 8;
        out[(size_t)o * N_OUT + n0 + lane] = tile[lane][o] * rd;
    }
}

// ---------------- launch ------------------------------------------------------
extern "C" void kernel_launch(void* const* d_in, const int* in_sizes, int n_in,
                              void* d_out, int out_size)
{
    const float* x     = (const float*)d_in[0];
    const int*   edges = (const int*)  d_in[1];
    const float* W     = (const float*)d_in[2];
    const float* b     = (const float*)d_in[3];
    const float* att   = (const float*)d_in[4];
    const float* alpha = (const float*)d_in[5];
    float* out = (float*)d_out;

    wcvt_kernel<<<64, 256>>>(W);
    gemm_kernel<<<GEMM_BLOCKS, 256>>>(x, b, att, alpha);
    scatter_kernel<<<N_EDGES / 8, 256>>>(edges);
    finalize_kernel<<<N_OUT / 32, 256>>>(out);
}

// round 10
// speedup vs baseline: 2.5090x; 1.5353x over previous
#include <cuda_runtime.h>
#include <cuda_fp16.h>
#include <cuda_bf16.h>
#include <cstdint>
#include <cstddef>

#define N_SRC   100000
#define N_OUT   100000
#define N_EDGES 1600000
#define C       128

// ---------------- scratch (device globals; no allocation allowed) ------------
__device__ __half        g_Wxh[(size_t)N_SRC * C];  // node-major fp16 Wx
__device__ __half        g_numh[(size_t)N_OUT * C]; // fp16 accumulators, 25.6 MB
__device__ float         g_expa[N_SRC];
__device__ float         g_den[N_OUT];
__device__ __nv_bfloat16 g_Whi[C * C];              // W bf16 hi, row-major [o][k]
__device__ __nv_bfloat16 g_Wlo[C * C];              // W bf16 lo

// ---------------- kernel 0: one-time W split to bf16 hi/lo -------------------
__global__ void wcvt_kernel(const float* __restrict__ W)
{
    const int i = blockIdx.x * 256 + threadIdx.x;   // 0..16383
    const float f = W[i];
    const __nv_bfloat16 hb = __float2bfloat16(f);
    g_Whi[i] = hb;
    g_Wlo[i] = __float2bfloat16(f - __bfloat162float(hb));
}

// ---------------- tensor-core GEMM helpers -----------------------------------
#define LDSM_X4(r0, r1, r2, r3, addr)                                          \
    asm volatile("ldmatrix.sync.aligned.m8n8.x4.shared.b16 {%0,%1,%2,%3},[%4];"\
                 : "=r"(r0), "=r"(r1), "=r"(r2), "=r"(r3) : "r"(addr))

#define LDSM_X4_T(r0, r1, r2, r3, addr)                                        \
    asm volatile("ldmatrix.sync.aligned.m8n8.x4.trans.shared.b16 {%0,%1,%2,%3},[%4];"\
                 : "=r"(r0), "=r"(r1), "=r"(r2), "=r"(r3) : "r"(addr))

#define MMA_BF16(c, a0, a1, a2, a3, b0, b1)                                    \
    asm volatile("mma.sync.aligned.m16n8k16.row.col.f32.bf16.bf16.f32 "        \
                 "{%0,%1,%2,%3},{%4,%5,%6,%7},{%8,%9},{%0,%1,%2,%3};"          \
                 : "+f"(c[0]), "+f"(c[1]), "+f"(c[2]), "+f"(c[3])              \
                 : "r"(a0), "r"(a1), "r"(a2), "r"(a3), "r"(b0), "r"(b1))

__device__ __forceinline__ void cvt_hilo4(float4 v, unsigned& hi0, unsigned& hi1,
                                          unsigned& lo0, unsigned& lo1)
{
    float f[4] = {v.x, v.y, v.z, v.w};
    unsigned short h[4], l[4];
#pragma unroll
    for (int i = 0; i < 4; i++) {
        __nv_bfloat16 hb = __float2bfloat16(f[i]);
        __nv_bfloat16 lb = __float2bfloat16(f[i] - __bfloat162float(hb));
        h[i] = __bfloat16_as_ushort(hb);
        l[i] = __bfloat16_as_ushort(lb);
    }
    hi0 = ((unsigned)h[1] << 16) | h[0];
    hi1 = ((unsigned)h[3] << 16) | h[2];
    lo0 = ((unsigned)l[1] << 16) | l[0];
    lo1 = ((unsigned)l[3] << 16) | l[2];
}

// ---------------- kernel 1: Wx = W @ x + b via bf16-split mma.sync -----------
#define A_PITCH 40    // 32 k + 8 pad (bf16)
#define B_PITCH 136   // 128 n + 8 pad (bf16)
#define GEMM_BLOCKS ((N_SRC + 127) / 128)     // 782

__global__ __launch_bounds__(256, 2) void gemm_kernel(
    const float* __restrict__ x,      // (C, N_SRC)
    const float* __restrict__ b,      // (C,)
    const float* __restrict__ att,    // (C,)
    const float* __restrict__ alphap) // scalar
{
    __shared__ __align__(16) unsigned char sbuf[37888];
    __nv_bfloat16* As_hi = reinterpret_cast<__nv_bfloat16*>(sbuf);          // [128][40]
    __nv_bfloat16* As_lo = reinterpret_cast<__nv_bfloat16*>(sbuf + 10240);
    __nv_bfloat16* Bs_hi = reinterpret_cast<__nv_bfloat16*>(sbuf + 20480);  // [32][136]
    __nv_bfloat16* Bs_lo = reinterpret_cast<__nv_bfloat16*>(sbuf + 29184);
    __half*        S     = reinterpret_cast<__half*>(sbuf);                 // epilogue [128][136]
    __shared__ float bsh[128], ash[128], sdot[128];

    const int tid  = threadIdx.x;
    const int w    = tid >> 5;
    const int lane = tid & 31;
    const int nbase = blockIdx.x * 128;

    // ---- fused zeroing of numh/den ----
    {
        const unsigned gi  = blockIdx.x * 256 + tid;
        const unsigned gst = GEMM_BLOCKS * 256;
        uint4* np = reinterpret_cast<uint4*>(g_numh);
        const unsigned n8 = (unsigned)((size_t)N_OUT * C / 8);   // uint4 = 8 halves
        const uint4 z = make_uint4(0u, 0u, 0u, 0u);
        for (unsigned k = gi; k < n8; k += gst)
            np[k] = z;
        for (unsigned k = gi; k < N_OUT; k += gst)
            g_den[k] = 0.f;
    }

    if (tid < 128) { bsh[tid] = b[tid]; ash[tid] = att[tid]; sdot[tid] = 0.f; }
    const float alpha = __ldg(alphap);

    const unsigned saAhi = (unsigned)__cvta_generic_to_shared(As_hi);
    const unsigned saAlo = (unsigned)__cvta_generic_to_shared(As_lo);
    const unsigned saBhi = (unsigned)__cvta_generic_to_shared(Bs_hi);
    const unsigned saBlo = (unsigned)__cvta_generic_to_shared(Bs_lo);

    const int lrow  = lane & 15;
    const int lcol8 = (lane >> 4) * 8;

    const int ow = w & 1;        // o-half: 64 o
    const int nw = w >> 1;       // n-quarter: 32 n
    const int nb = nw * 32;
    const int ob = ow * 64;

    float cc[4][4][4];
#pragma unroll
    for (int mt = 0; mt < 4; mt++)
#pragma unroll
        for (int nt = 0; nt < 4; nt++)
#pragma unroll
            for (int j = 0; j < 4; j++) cc[mt][nt][j] = 0.f;

    for (int kc = 0; kc < 4; kc++) {
        const int kbase = kc * 32;
        __syncthreads();

#pragma unroll
        for (int it = 0; it < 2; it++) {
            const int idx = it * 256 + tid;
            const int o   = idx >> 2;
            const int kq  = (idx & 3) * 8;
            *reinterpret_cast<uint4*>(&As_hi[o * A_PITCH + kq]) =
                *reinterpret_cast<const uint4*>(&g_Whi[o * C + kbase + kq]);
            *reinterpret_cast<uint4*>(&As_lo[o * A_PITCH + kq]) =
                *reinterpret_cast<const uint4*>(&g_Wlo[o * C + kbase + kq]);
        }

#pragma unroll
        for (int it = 0; it < 4; it++) {
            const int r = it * 8 + w;
            const int n = nbase + lane * 4;
            float4 v = make_float4(0.f, 0.f, 0.f, 0.f);
            if (n < N_SRC)
                v = *reinterpret_cast<const float4*>(&x[(size_t)(kbase + r) * N_SRC + n]);
            unsigned h0, h1, l0, l1;
            cvt_hilo4(v, h0, h1, l0, l1);
            unsigned* dh = reinterpret_cast<unsigned*>(&Bs_hi[r * B_PITCH + lane * 4]);
            unsigned* dl = reinterpret_cast<unsigned*>(&Bs_lo[r * B_PITCH + lane * 4]);
            dh[0] = h0; dh[1] = h1;
            dl[0] = l0; dl[1] = l1;
        }
        __syncthreads();

#pragma unroll
        for (int ks = 0; ks < 2; ks++) {
            const int ko = ks * 16;
            const unsigned boff0 = (unsigned)(((ko + lrow) * B_PITCH + nb + lcol8) * 2);
            const unsigned boff1 = (unsigned)(((ko + lrow) * B_PITCH + nb + 16 + lcol8) * 2);
            unsigned bh[8], bl[8];
            LDSM_X4_T(bh[0], bh[1], bh[2], bh[3], saBhi + boff0);
            LDSM_X4_T(bh[4], bh[5], bh[6], bh[7], saBhi + boff1);
            LDSM_X4_T(bl[0], bl[1], bl[2], bl[3], saBlo + boff0);
            LDSM_X4_T(bl[4], bl[5], bl[6], bl[7], saBlo + boff1);

#pragma unroll
            for (int mt = 0; mt < 4; mt++) {
                const unsigned aoff =
                    (unsigned)(((ob + mt * 16 + lrow) * A_PITCH + ko + lcol8) * 2);
                unsigned ah0, ah1, ah2, ah3, al0, al1, al2, al3;
                LDSM_X4(ah0, ah1, ah2, ah3, saAhi + aoff);
                LDSM_X4(al0, al1, al2, al3, saAlo + aoff);

#pragma unroll
                for (int nt = 0; nt < 4; nt++) {
                    MMA_BF16(cc[mt][nt], ah0, ah1, ah2, ah3, bh[2*nt], bh[2*nt+1]);
                    MMA_BF16(cc[mt][nt], ah0, ah1, ah2, ah3, bl[2*nt], bl[2*nt+1]);
                    MMA_BF16(cc[mt][nt], al0, al1, al2, al3, bh[2*nt], bh[2*nt+1]);
                }
            }
        }
    }

    __syncthreads();   // mainloop smem dead; S may alias it

    // ---- epilogue: bias, att-dot partials, fp16 staging ----
    const int g  = lane >> 2;
    const int tg = lane & 3;
    float part[4][2];
#pragma unroll
    for (int nt = 0; nt < 4; nt++) { part[nt][0] = 0.f; part[nt][1] = 0.f; }

#pragma unroll
    for (int mt = 0; mt < 4; mt++) {
        const int o0 = ob + mt * 16 + g;
        const int o1 = o0 + 8;
        const float b0 = bsh[o0], b1 = bsh[o1];
        const float a0 = ash[o0], a1 = ash[o1];
#pragma unroll
        for (int nt = 0; nt < 4; nt++) {
            const float c0 = cc[mt][nt][0] + b0;
            const float c1 = cc[mt][nt][1] + b0;
            const float c2 = cc[mt][nt][2] + b1;
            const float c3 = cc[mt][nt][3] + b1;
            const int n0 = nb + nt * 8 + tg * 2;
            S[n0 * B_PITCH + o0]       = __float2half(c0);
            S[(n0 + 1) * B_PITCH + o0] = __float2half(c1);
            S[n0 * B_PITCH + o1]       = __float2half(c2);
            S[(n0 + 1) * B_PITCH + o1] = __float2half(c3);
            part[nt][0] += a0 * c0 + a1 * c2;
            part[nt][1] += a0 * c1 + a1 * c3;
        }
    }

#pragma unroll
    for (int m = 4; m < 32; m <<= 1)
#pragma unroll
        for (int nt = 0; nt < 4; nt++)
#pragma unroll
            for (int j = 0; j < 2; j++)
                part[nt][j] += __shfl_xor_sync(0xFFFFFFFFu, part[nt][j], m);

    if (lane < 4) {
#pragma unroll
        for (int nt = 0; nt < 4; nt++)
#pragma unroll
            for (int j = 0; j < 2; j++)
                atomicAdd(&sdot[nb + nt * 8 + lane * 2 + j], part[nt][j]);
    }
    __syncthreads();

    if (tid < 128) {
        const int n = nbase + tid;
        if (n < N_SRC) {
            float a = sdot[tid];
            a = (a >= 0.f) ? a : alpha * a;
            g_expa[n] = __expf(a);
        }
    }

    for (int idx = tid; idx < 128 * 16; idx += 256) {
        const int n  = idx >> 4;
        const int c8 = (idx & 15) * 8;
        const int gn = nbase + n;
        if (gn < N_SRC)
            *reinterpret_cast<uint4*>(&g_Wxh[(size_t)gn * C + c8]) =
                *reinterpret_cast<const uint4*>(&S[n * B_PITCH + c8]);
    }
}

// ---------------- kernel 2: edge scatter (16 lanes/edge, fp16x2 v4 reds) -----
// Lane covers 8 channels (16B). Scale computed in fp32, converted once.
__global__ __launch_bounds__(256) void scatter_kernel(const int* __restrict__ edges)
{
    const int e = blockIdx.x * 16 + (threadIdx.x >> 4);
    const int l = threadIdx.x & 15;

    const int2 ts = reinterpret_cast<const int2*>(edges)[e];
    const int tgt = ts.x;
    const int src = ts.y;

    const float ex = __ldg((const float*)&g_expa[src]);

    const uint4 h = *reinterpret_cast<const uint4*>(&g_Wxh[(size_t)src * C + l * 8]);
    unsigned p[4];
    {
        const unsigned hv[4] = {h.x, h.y, h.z, h.w};
#pragma unroll
        for (int i = 0; i < 4; i++) {
            float2 f = __half22float2(*reinterpret_cast<const __half2*>(&hv[i]));
            __half2 r = __floats2half2_rn(f.x * ex, f.y * ex);
            p[i] = *reinterpret_cast<unsigned*>(&r);
        }
    }

    __half* np = &g_numh[(size_t)tgt * C + l * 8];
    asm volatile("red.global.add.noftz.v4.f16x2 [%0], {%1, %2, %3, %4};"
                 :: "l"(np), "r"(p[0]), "r"(p[1]), "r"(p[2]), "r"(p[3])
                 : "memory");

    if (l == 0)
        atomicAdd(&g_den[tgt], ex);
}

// ---------------- kernel 3: normalize + transpose, 32 n x 128 o per block ----
__global__ __launch_bounds__(256) void finalize_kernel(float* __restrict__ out)
{
    __shared__ float tile[32][129];
    __shared__ float dsh[32];

    const int tid  = threadIdx.x;
    const int lane = tid & 31;
    const int w    = tid >> 5;
    const int n0   = blockIdx.x * 32;

    if (tid < 32) {
        float d = g_den[n0 + tid];
        dsh[tid] = (d == 0.f) ? 1.f : d;
    }

    // load: 32 rows x 128 halves = 512 uint4, 2 per thread (coalesced)
#pragma unroll
    for (int it = 0; it < 2; it++) {
        const int idx = it * 256 + tid;       // 0..511
        const int n   = idx >> 4;             // row 0..31
        const int o8  = (idx & 15) * 8;       // col group of 8
        const uint4 hv =
            *reinterpret_cast<const uint4*>(&g_numh[(size_t)(n0 + n) * C + o8]);
        const unsigned hs[4] = {hv.x, hv.y, hv.z, hv.w};
#pragma unroll
        for (int i = 0; i < 4; i++) {
            const float2 f = __half22float2(*reinterpret_cast<const __half2*>(&hs[i]));
            tile[n][o8 + i * 2 + 0] = f.x;
            tile[n][o8 + i * 2 + 1] = f.y;
        }
    }
    __syncthreads();

    const float rd = 1.f / dsh[lane];
#pragma unroll
    for (int r = 0; r < 16; r++) {
        const int o = w + r * 8;
        out[(size_t)o * N_OUT + n0 + lane] = tile[lane][o] * rd;
    }
}

// ---------------- launch ------------------------------------------------------
extern "C" void kernel_launch(void* const* d_in, const int* in_sizes, int n_in,
                              void* d_out, int out_size)
{
    const float* x     = (const float*)d_in[0];
    const int*   edges = (const int*)  d_in[1];
    const float* W     = (const float*)d_in[2];
    const float* b     = (const float*)d_in[3];
    const float* att   = (const float*)d_in[4];
    const float* alpha = (const float*)d_in[5];
    float* out = (float*)d_out;

    wcvt_kernel<<<64, 256>>>(W);
    gemm_kernel<<<GEMM_BLOCKS, 256>>>(x, b, att, alpha);
    scatter_kernel<<<N_EDGES / 16, 256>>>(edges);
    finalize_kernel<<<N_OUT / 32, 256>>>(out);
}